// round 3
// baseline (speedup 1.0000x reference)
#include <cuda_runtime.h>

// EMA scan: s_t = 0.9*s_{t-1} + 0.1*x_t
// x: (1024, 32, 1024) f32, state: (32, 1024) f32
// out buffer: out (1024*32768 floats) then final_state (32768 floats)
//
// float4 vectorized: one thread owns 4 consecutive channels (4 independent
// EMA chains -> 4-way FFMA ILP, LDG.128/STG.128).
// T split in 2 chunks at t=576; chunk 1 warms up 128 steps from s=0
// (decay 0.9^128 ~ 1.4e-6 << 1e-3 tolerance). Both chunks load 576 steps.
// 8-deep double-buffered prefetch keeps LDG.128s continuously in flight.

#define T_STEPS 1024
#define N_CH    32768
#define N_V     8192        // N_CH / 4 float4 columns
#define U       8
#define SPLIT   576
#define WARM    128

__device__ __forceinline__
float4 ema4(float4 s, float4 xv)
{
    s.x = fmaf(s.x, 0.9f, xv.x * 0.1f);
    s.y = fmaf(s.y, 0.9f, xv.y * 0.1f);
    s.z = fmaf(s.z, 0.9f, xv.z * 0.1f);
    s.w = fmaf(s.w, 0.9f, xv.w * 0.1f);
    return s;
}

__device__ __forceinline__
float4 run_span4(const float4* __restrict__ xp, float4* __restrict__ op,
                 float4 s, int t0, int t1, bool do_store)
{
    float4 cur[U], nxt[U];

    #pragma unroll
    for (int u = 0; u < U; u++)
        cur[u] = __ldcs(xp + (size_t)(t0 + u) * N_V);

    #pragma unroll 1
    for (int t = t0; t < t1; t += U) {
        const int tn = t + U;
        if (tn < t1) {
            #pragma unroll
            for (int u = 0; u < U; u++)
                nxt[u] = __ldcs(xp + (size_t)(tn + u) * N_V);
        }
        #pragma unroll
        for (int u = 0; u < U; u++) {
            s = ema4(s, cur[u]);
            if (do_store)
                __stcs(op + (size_t)(t + u) * N_V, s);
        }
        #pragma unroll
        for (int u = 0; u < U; u++)
            cur[u] = nxt[u];
    }
    return s;
}

__global__ __launch_bounds__(64, 8)
void ema_scan_kernel(const float4* __restrict__ x,
                     const float4* __restrict__ state,
                     float4* __restrict__ out)
{
    const int tid  = blockIdx.x * 64 + threadIdx.x;   // 0..16383
    const int c4   = tid & (N_V - 1);                 // float4 column
    const int half = tid >> 13;                       // 0 or 1

    const float4* xp = x + c4;
    float4*       op = out + c4;

    if (half == 0) {
        // chunk 0: exact scan [0, SPLIT)
        float4 s = state[c4];
        run_span4(xp, op, s, 0, SPLIT, true);
    } else {
        // chunk 1: warm-up [SPLIT-WARM, SPLIT) from 0, then store [SPLIT, T)
        float4 s = make_float4(0.f, 0.f, 0.f, 0.f);
        s = run_span4(xp, op, s, SPLIT - WARM, SPLIT, false);
        s = run_span4(xp, op, s, SPLIT, T_STEPS, true);
        out[(size_t)T_STEPS * N_V + c4] = s;   // final_state
    }
}

extern "C" void kernel_launch(void* const* d_in, const int* in_sizes, int n_in,
                              void* d_out, int out_size)
{
    const float4* x     = (const float4*)d_in[0];
    const float4* state = (const float4*)d_in[1];
    float4*       out   = (float4*)d_out;

    dim3 block(64);
    dim3 grid((2 * N_V) / 64);   // 256 CTAs
    ema_scan_kernel<<<grid, block>>>(x, state, out);
}

// round 4
// speedup vs baseline: 1.1280x; 1.1280x over previous
#include <cuda_runtime.h>

// EMA scan: s_t = 0.9*s_{t-1} + 0.1*x_t
// x: (1024, 32, 1024) f32, state: (32, 1024) f32
// out buffer: out (1024*32768 floats) then final_state (32768 floats)
//
// Latency-bound streaming kernel -> maximize warp-level concurrency.
// T split into 4 chunks of 256. Chunk k>0 warms up 96 steps from s=0
// (decay 0.9^96 ~ 4e-5 << 1e-3 tolerance) before storing its span.
// 131072 threads (4096 warps), scalar f32, 8-deep load batches.

#define T_STEPS 1024
#define N_CH    32768
#define U       8
#define CHUNK   256          // T_STEPS / 4
#define WARM    96

__device__ __forceinline__
float run_span(const float* __restrict__ xp, float* __restrict__ op,
               float s, int t0, int t1, bool do_store)
{
    float xs[U];
    #pragma unroll 1
    for (int t = t0; t < t1; t += U) {
        #pragma unroll
        for (int u = 0; u < U; u++)
            xs[u] = __ldcs(xp + (size_t)(t + u) * N_CH);
        #pragma unroll
        for (int u = 0; u < U; u++) {
            s = fmaf(s, 0.9f, xs[u] * 0.1f);
            if (do_store)
                __stcs(op + (size_t)(t + u) * N_CH, s);
        }
    }
    return s;
}

__global__ __launch_bounds__(256, 4)
void ema_scan_kernel(const float* __restrict__ x,
                     const float* __restrict__ state,
                     float* __restrict__ out)
{
    const int tid   = blockIdx.x * 256 + threadIdx.x;  // 0..131071
    const int c     = tid & (N_CH - 1);                // channel
    const int chunk = tid >> 15;                       // 0..3

    const float* xp = x + c;
    float*       op = out + c;

    const int start = chunk * CHUNK;

    float s;
    if (chunk == 0) {
        s = state[c];
    } else {
        s = run_span(xp, op, 0.0f, start - WARM, start, false);
    }

    s = run_span(xp, op, s, start, start + CHUNK, true);

    if (chunk == 3)
        out[(size_t)T_STEPS * N_CH + c] = s;   // final_state
}

extern "C" void kernel_launch(void* const* d_in, const int* in_sizes, int n_in,
                              void* d_out, int out_size)
{
    const float* x     = (const float*)d_in[0];
    const float* state = (const float*)d_in[1];
    float*       out   = (float*)d_out;

    dim3 block(256);
    dim3 grid((4 * N_CH) / 256);   // 512 CTAs: 4 T-chunks x 32768 channels
    ema_scan_kernel<<<grid, block>>>(x, state, out);
}

// round 5
// speedup vs baseline: 1.5161x; 1.3441x over previous
#include <cuda_runtime.h>
#include <cstdint>

// EMA scan: s_t = 0.9*s_{t-1} + 0.1*x_t
// x: (1024, 32, 1024) f32, state: (32, 1024) f32
// out: out (1024*32768 floats) then final_state (32768 floats)
//
// Single exact pass (zero extra traffic). Loads decoupled from the serial
// recurrence via a 4-stage cp.async (LDGSTS) shared-memory pipeline:
// CTA = 128 threads = 128 consecutive channels; tile = 32 timesteps x 128 ch
// (16 KB); 4 stages = 64 KB dynamic SMEM; one __syncthreads per tile.

#define T_STEPS 1024
#define N_CH    32768
#define CH_CTA  128
#define TT      32                    // timesteps per stage
#define STAGES  4
#define NTILES  (T_STEPS / TT)        // 32
#define STAGE_BYTES (TT * CH_CTA * 4) // 16384

__device__ __forceinline__ void cp_async16(uint32_t smem_addr, const void* gmem) {
    asm volatile("cp.async.cg.shared.global [%0], [%1], 16;"
                 :: "r"(smem_addr), "l"(gmem));
}
__device__ __forceinline__ void cp_commit() {
    asm volatile("cp.async.commit_group;");
}
__device__ __forceinline__ void cp_wait2() {
    asm volatile("cp.async.wait_group 2;");   // STAGES-2
}

__global__ __launch_bounds__(CH_CTA, 2)
void ema_scan_kernel(const float* __restrict__ x,
                     const float* __restrict__ state,
                     float* __restrict__ out)
{
    extern __shared__ float smem[];   // [STAGES][TT][CH_CTA]

    const int tid = threadIdx.x;                 // 0..127
    const int c0  = blockIdx.x * CH_CTA;
    const int c   = c0 + tid;

    // loader mapping: 128 threads x 16B = 2 KB = 4 rows per round, 8 rounds/stage
    const int f4col  = tid & 31;                 // 0..31 (float4 column)
    const int rowgrp = tid >> 5;                 // 0..3

    uint32_t smem_base;
    asm("{ .reg .u64 t; cvta.to.shared.u64 t, %1; cvt.u32.u64 %0, t; }"
        : "=r"(smem_base) : "l"(smem));

    const char* gbase = (const char*)(x + (size_t)c0 + f4col * 4);

    // issue one stage's loads: tile k -> buffer (k % STAGES)
    auto issue_tile = [&](int k) {
        const uint32_t sbuf = smem_base + (uint32_t)(k & (STAGES - 1)) * STAGE_BYTES
                            + rowgrp * (CH_CTA * 4) + f4col * 16;
        const char* g = gbase + ((size_t)k * TT + rowgrp) * (N_CH * 4);
        #pragma unroll
        for (int r = 0; r < TT / 4; r++) {       // 8 rounds, rows rowgrp+4r
            cp_async16(sbuf + (uint32_t)r * 4 * CH_CTA * 4,
                       g + (size_t)r * 4 * N_CH * 4);
        }
    };

    // prologue: stages 0..STAGES-2, one commit group each
    #pragma unroll
    for (int k = 0; k < STAGES - 1; k++) { issue_tile(k); cp_commit(); }

    float s = state[c];
    float* op = out + c;

    #pragma unroll 1
    for (int k = 0; k < NTILES; k++) {
        cp_wait2();            // tile k's group complete (<= STAGES-2 pending)
        __syncthreads();       // visibility + guards reuse of buf[(k-1)%S]

        if (k + STAGES - 1 < NTILES) issue_tile(k + STAGES - 1);
        cp_commit();           // always commit (keeps group accounting aligned)

        const float* buf = smem + (k & (STAGES - 1)) * (TT * CH_CTA);
        #pragma unroll
        for (int t = 0; t < TT; t++) {
            s = fmaf(s, 0.9f, buf[t * CH_CTA + tid] * 0.1f);
            __stcs(op + (size_t)(k * TT + t) * N_CH, s);
        }
    }

    out[(size_t)T_STEPS * N_CH + c] = s;   // final_state
}

extern "C" void kernel_launch(void* const* d_in, const int* in_sizes, int n_in,
                              void* d_out, int out_size)
{
    const float* x     = (const float*)d_in[0];
    const float* state = (const float*)d_in[1];
    float*       out   = (float*)d_out;

    static bool attr_set = false;
    if (!attr_set) {
        cudaFuncSetAttribute(ema_scan_kernel,
                             cudaFuncAttributeMaxDynamicSharedMemorySize,
                             STAGES * STAGE_BYTES);
        attr_set = true;
    }

    dim3 block(CH_CTA);
    dim3 grid(N_CH / CH_CTA);   // 256 CTAs
    ema_scan_kernel<<<grid, block, STAGES * STAGE_BYTES>>>(x, state, out);
}